// round 14
// baseline (speedup 1.0000x reference)
#include <cuda_runtime.h>
#include <cuda_bf16.h>
#include <math.h>

#define NN 4096
#define EE 65536
#define HH 128
#define RR 32
#define NB 2048
#define NH (NN*HH)

// ---------------- scratch (device globals; no runtime allocation) ----------------
__device__ __align__(16) float g_cm[10*NH];     // comp-major tensor components for mix GEMM
__device__ __align__(16) float g_T1[128*HH];
__device__ __align__(16) float g_T2[128*HH];
__device__ __align__(16) float4 g_tab4[NB*HH];  // per x-node, per h: (dot1,dot2,dot3,-)
__device__ __align__(16) float g_nrm[NH];
__device__ __align__(16) float g_h[NN*256];
__device__ __align__(16) float g_scal[NN*384];
__device__ __align__(16) float g_mix[10*NH];
__device__ __align__(16) float g_xln[NN*384];
__device__ __align__(16) float g_s1[NN*HH];
__device__ __align__(16) float g_s2[NN*64];
// counting-sort scratch. g_cnt is zero at module load; k_scan re-zeroes it
// after reading, so every kernel_launch call (and graph replay) sees zeros.
__device__ int g_cnt[NN];
__device__ int g_off[NN+1];
__device__ int g_pos[NN];
// pre-sorted per-edge payload: {ux,uy,uz,cut} and {u(table coord), zt}
__device__ __align__(16) float4 g_pay1[EE];
__device__ __align__(16) float2 g_pay2[EE];

// Device-side resolution of scratch buffers (host must never pass __device__ globals).
__device__ __forceinline__ float* gptr(int id) {
    switch (id) {
        case 0: return g_nrm;
        case 1: return g_h;
        case 2: return g_scal;
        case 3: return g_xln;
        case 4: return g_s1;
        case 5: return g_s2;
    }
    return nullptr;
}

__device__ __forceinline__ float warp_sum(float v) {
    #pragma unroll
    for (int o = 16; o > 0; o >>= 1) v += __shfl_xor_sync(0xffffffffu, v, o);
    return v;
}

// ---------------- tf32 helpers ----------------
__device__ __forceinline__ void tf32split(float x, unsigned &hi, unsigned &lo) {
    unsigned h;
    asm("cvt.rna.tf32.f32 %0, %1;" : "=r"(h) : "f"(x));
    float r = x - __uint_as_float(h);
    unsigned l;
    asm("cvt.rna.tf32.f32 %0, %1;" : "=r"(l) : "f"(r));
    hi = h; lo = l;
}

__device__ __forceinline__ void mma_tf32(float* d, const unsigned* a, const unsigned* b) {
    asm volatile(
        "mma.sync.aligned.m16n8k8.row.col.f32.tf32.tf32.f32 "
        "{%0,%1,%2,%3}, {%4,%5,%6,%7}, {%8,%9}, {%0,%1,%2,%3};\n"
        : "+f"(d[0]), "+f"(d[1]), "+f"(d[2]), "+f"(d[3])
        : "r"(a[0]), "r"(a[1]), "r"(a[2]), "r"(a[3]), "r"(b[0]), "r"(b[1]));
}

// ---------------- T1/T2 tables: fold emb + emb2 (+bias) over the 128 atom types ----------------
__global__ void k_tables(const float* __restrict__ emb_w, const float* __restrict__ emb2_w,
                         const float* __restrict__ emb2_b) {
    int t = blockIdx.x;          // atom type 0..127
    int h = threadIdx.x;         // 0..127
    __shared__ float se[128];
    se[h] = emb_w[t*HH + h];
    __syncthreads();
    float s1 = emb2_b[h], s2 = 0.f;
    #pragma unroll 8
    for (int k = 0; k < 128; k++) {
        s1 = fmaf(emb2_w[h*256 + k],       se[k], s1);
        s2 = fmaf(emb2_w[h*256 + 128 + k], se[k], s2);
    }
    g_T1[t*HH + h] = s1;
    g_T2[t*HH + h] = s2;
}

// ---------------- RBF->dp matvec lookup table over x = exp(-alpha*d) ----------------
__global__ void k_btab(const float* __restrict__ dp1w, const float* __restrict__ dp2w,
                       const float* __restrict__ dp3w,
                       float m0, float dm, float beta, float x0, float dstep) {
    __shared__ float srb[8*32];
    int h  = threadIdx.x;          // 0..127
    int b0 = blockIdx.x * 8;       // 8 nodes per block
    for (int k = h; k < 8*32; k += 128) {
        int bin = k >> 5, r = k & 31;
        float xr = x0 + (float)(b0 + bin) * dstep;
        float df = xr - (m0 + dm * (float)r);
        srb[k] = __expf(-beta * df * df);
    }
    __syncthreads();
    const float4* p1 = (const float4*)(dp1w + h*RR);
    const float4* p2 = (const float4*)(dp2w + h*RR);
    const float4* p3 = (const float4*)(dp3w + h*RR);
    #pragma unroll
    for (int bin = 0; bin < 8; bin++) {
        float v1 = 0.f, v2 = 0.f, v3 = 0.f;
        #pragma unroll
        for (int q = 0; q < 8; q++) {
            float4 f1 = __ldg(&p1[q]);
            float4 f2 = __ldg(&p2[q]);
            float4 f3 = __ldg(&p3[q]);
            const float* sb = &srb[bin*32 + q*4];
            v1 = fmaf(f1.x, sb[0], fmaf(f1.y, sb[1], fmaf(f1.z, sb[2], fmaf(f1.w, sb[3], v1))));
            v2 = fmaf(f2.x, sb[0], fmaf(f2.y, sb[1], fmaf(f2.z, sb[2], fmaf(f2.w, sb[3], v2))));
            v3 = fmaf(f3.x, sb[0], fmaf(f3.y, sb[1], fmaf(f3.z, sb[2], fmaf(f3.w, sb[3], v3))));
        }
        g_tab4[(size_t)(b0 + bin)*HH + h] = make_float4(v1, v2, v3, 0.f);
    }
}

// ---------------- counting sort: histogram ----------------
__global__ void k_hist(const int* __restrict__ eidx) {
    int e = blockIdx.x * blockDim.x + threadIdx.x;
    if (e < EE) atomicAdd(&g_cnt[eidx[e]], 1);
}

// ---------------- scan only (single 1024-thread block over 4096 counters) ----------------
__global__ void k_scan() {
    __shared__ int ssum[32];
    int t = threadIdx.x, lane = t & 31, w = t >> 5;
    int c0 = g_cnt[t*4+0], c1 = g_cnt[t*4+1], c2 = g_cnt[t*4+2], c3 = g_cnt[t*4+3];
    g_cnt[t*4+0] = 0; g_cnt[t*4+1] = 0; g_cnt[t*4+2] = 0; g_cnt[t*4+3] = 0;
    int tot = c0 + c1 + c2 + c3;
    int inc = tot;
    #pragma unroll
    for (int o = 1; o < 32; o <<= 1) {
        int v = __shfl_up_sync(0xffffffffu, inc, o);
        if (lane >= o) inc += v;
    }
    if (lane == 31) ssum[w] = inc;
    __syncthreads();
    if (w == 0) {
        int i2 = ssum[lane];
        #pragma unroll
        for (int o = 1; o < 32; o <<= 1) {
            int u = __shfl_up_sync(0xffffffffu, i2, o);
            if (lane >= o) i2 += u;
        }
        ssum[lane] = i2;
    }
    __syncthreads();
    int base = (w ? ssum[w-1] : 0) + inc - tot;       // exclusive prefix
    int o0 = base, o1 = base + c0, o2 = o1 + c1, o3 = o2 + c2;
    g_off[t*4+0] = o0; g_off[t*4+1] = o1; g_off[t*4+2] = o2; g_off[t*4+3] = o3;
    g_pos[t*4+0] = o0; g_pos[t*4+1] = o1; g_pos[t*4+2] = o2; g_pos[t*4+3] = o3;
    if (t == 1023) g_off[NN] = o3 + c3;
}

// ---------------- scatter: per-edge prologue computed here, written to sorted slot ----------------
__global__ void k_scatter(const int* __restrict__ eidx, const float* __restrict__ edge_vec,
                          const int* __restrict__ z, float x0, float invD) {
    const float PI_CU = 3.14159265358979f / 4.5f;
    const float ALPHA = 5.0f / 4.5f;
    int e = blockIdx.x * blockDim.x + threadIdx.x;
    if (e >= EE) return;
    int s = __ldg(&eidx[e]);
    int slot = atomicAdd(&g_pos[s], 1);
    float ex = __ldg(&edge_vec[e*3+0]);
    float ey = __ldg(&edge_vec[e*3+1]);
    float ez = __ldg(&edge_vec[e*3+2]);
    float d  = sqrtf(ex*ex + ey*ey + ez*ez);
    float inv = 1.0f / d;
    float cut = (d < 4.5f) ? 0.5f*(cosf(PI_CU*d) + 1.0f) : 0.0f;
    float u   = (__expf(-ALPHA*d) - x0) * invD;
    int zt = __ldg(&z[__ldg(&eidx[EE + e])]);
    g_pay1[slot] = make_float4(ex*inv, ey*inv, ez*inv, cut);
    g_pay2[slot] = make_float2(u, __int_as_float(zt));
}

// ---------------- gather: 2 warps per atom, prefetched, table-interpolated ----------------
// Each atom's edge list is split stride-2 across a warp pair; partial 10-comp
// accumulators merge through smem; even warp runs the tn+LN+split epilogue.
__global__ void __launch_bounds__(128) k_gather(
    const float* __restrict__ dp1b, const float* __restrict__ dp2b,
    const float* __restrict__ dp3b, const int* __restrict__ z,
    const float* __restrict__ ig, const float* __restrict__ ib)
{
    __shared__ float sacc[2][10][4][32];     // [atomInBlk][comp][j][lane]
    int tid  = threadIdx.x;
    int lane = tid & 31, w = tid >> 5;
    int aib  = w >> 1;                       // atom within block (0..1)
    int sub  = w & 1;                        // warp half (0/1)
    int n = blockIdx.x * 2 + aib;
    int off0 = g_off[n];
    int endE = g_off[n+1];
    int zn   = __ldg(&z[n]);

    float t1h[4], b1h[4], b2h[4], b3h[4];
    #pragma unroll
    for (int j = 0; j < 4; j++) {
        int h = lane + 32*j;
        t1h[j] = g_T1[zn*HH + h];
        b1h[j] = __ldg(&dp1b[h]);
        b2h[j] = __ldg(&dp2b[h]);
        b3h[j] = __ldg(&dp3b[h]);
    }

    float aI[4], aAx[4], aAy[4], aAz[4];
    float aSxx[4], aSxy[4], aSxz[4], aSyy[4], aSyz[4], aSzz[4];
    #pragma unroll
    for (int j = 0; j < 4; j++) {
        aI[j]=0.f; aAx[j]=0.f; aAy[j]=0.f; aAz[j]=0.f;
        aSxx[j]=0.f; aSxy[j]=0.f; aSxz[j]=0.f; aSyy[j]=0.f; aSyz[j]=0.f; aSzz[j]=0.f;
    }

    // stride-2 interleaved split across the warp pair, payload double-buffered
    int i = off0 + sub;
    float4 nf1 = make_float4(0.f,0.f,0.f,0.f);
    float2 nf2 = make_float2(0.f,0.f);
    if (i < endE) { nf1 = __ldg(&g_pay1[i]); nf2 = __ldg(&g_pay2[i]); }
    for (; i < endE; i += 2) {
        float4 p1 = nf1;
        float2 p2 = nf2;
        int nx = i + 2;
        if (nx < endE) { nf1 = __ldg(&g_pay1[nx]); nf2 = __ldg(&g_pay2[nx]); }

        float cut = p1.w;
        if (cut == 0.0f) continue;
        float u = p2.x;
        int bin = (int)u;
        bin = (bin < 0) ? 0 : ((bin > NB-2) ? NB-2 : bin);
        float frac = u - (float)bin;
        int zt = __float_as_int(p2.y);

        float x = p1.x, y = p1.y, zc = p1.z;
        float tr3 = (x*x + y*y + zc*zc) * (1.0f/3.0f);
        float oxx = x*x - tr3, oyy = y*y - tr3, ozz = zc*zc - tr3;
        float oxy = x*y, oxz = x*zc, oyz = y*zc;

        const float4* rowL = g_tab4 + (size_t)bin*HH;
        const float4* rowH = rowL + HH;
        const float*  t2r  = g_T2 + zt*HH;

        #pragma unroll
        for (int j = 0; j < 4; j++) {
            int h = lane + 32*j;
            float4 lo = __ldg(&rowL[h]);
            float4 hi = __ldg(&rowH[h]);
            float t2  = __ldg(&t2r[h]);
            float c   = cut * (t1h[j] + t2);
            float w1 = fmaf(cut, fmaf(frac, hi.x - lo.x, lo.x), b1h[j]) * c;
            float w2 = fmaf(cut, fmaf(frac, hi.y - lo.y, lo.y), b2h[j]) * c;
            float w3 = fmaf(cut, fmaf(frac, hi.z - lo.z, lo.z), b3h[j]) * c;
            aI[j]  += w1;
            aAx[j]  = fmaf(w2, x,  aAx[j]);
            aAy[j]  = fmaf(w2, y,  aAy[j]);
            aAz[j]  = fmaf(w2, zc, aAz[j]);
            aSxx[j] = fmaf(w3, oxx, aSxx[j]);
            aSyy[j] = fmaf(w3, oyy, aSyy[j]);
            aSzz[j] = fmaf(w3, ozz, aSzz[j]);
            aSxy[j] = fmaf(w3, oxy, aSxy[j]);
            aSxz[j] = fmaf(w3, oxz, aSxz[j]);
            aSyz[j] = fmaf(w3, oyz, aSyz[j]);
        }
    }

    // merge the odd warp's partials into the even warp via smem
    if (sub == 1) {
        #pragma unroll
        for (int j = 0; j < 4; j++) {
            sacc[aib][0][j][lane] = aI[j];
            sacc[aib][1][j][lane] = aAx[j];
            sacc[aib][2][j][lane] = aAy[j];
            sacc[aib][3][j][lane] = aAz[j];
            sacc[aib][4][j][lane] = aSxx[j];
            sacc[aib][5][j][lane] = aSxy[j];
            sacc[aib][6][j][lane] = aSxz[j];
            sacc[aib][7][j][lane] = aSyy[j];
            sacc[aib][8][j][lane] = aSyz[j];
            sacc[aib][9][j][lane] = aSzz[j];
        }
    }
    __syncthreads();
    if (sub == 1) return;

    #pragma unroll
    for (int j = 0; j < 4; j++) {
        aI[j]   += sacc[aib][0][j][lane];
        aAx[j]  += sacc[aib][1][j][lane];
        aAy[j]  += sacc[aib][2][j][lane];
        aAz[j]  += sacc[aib][3][j][lane];
        aSxx[j] += sacc[aib][4][j][lane];
        aSxy[j] += sacc[aib][5][j][lane];
        aSxz[j] += sacc[aib][6][j][lane];
        aSyy[j] += sacc[aib][7][j][lane];
        aSyz[j] += sacc[aib][8][j][lane];
        aSzz[j] += sacc[aib][9][j][lane];
    }

    float tn[4];
    #pragma unroll
    for (int j = 0; j < 4; j++) {
        tn[j] = 3.f*aI[j]*aI[j]
              + 2.f*(aAx[j]*aAx[j] + aAy[j]*aAy[j] + aAz[j]*aAz[j])
              + aSxx[j]*aSxx[j] + aSyy[j]*aSyy[j] + aSzz[j]*aSzz[j]
              + 2.f*(aSxy[j]*aSxy[j] + aSxz[j]*aSxz[j] + aSyz[j]*aSyz[j]);
    }
    float s  = warp_sum(tn[0] + tn[1] + tn[2] + tn[3]);
    float mu = s * (1.0f/128.0f);
    float v = 0.f;
    #pragma unroll
    for (int j = 0; j < 4; j++) { float d = tn[j]-mu; v += d*d; }
    v = warp_sum(v) * (1.0f/128.0f);
    float rs = rsqrtf(v + 1e-5f);

    #pragma unroll
    for (int j = 0; j < 4; j++) {
        int h = lane + 32*j;
        size_t o = (size_t)n*HH + h;
        g_nrm[o] = (tn[j]-mu)*rs*__ldg(&ig[h]) + __ldg(&ib[h]);
        g_cm[0*NH+o] = aI[j];
        g_cm[1*NH+o] = aAx[j];  g_cm[2*NH+o] = aAy[j];  g_cm[3*NH+o] = aAz[j];
        g_cm[4*NH+o] = aSxx[j]; g_cm[5*NH+o] = aSxy[j]; g_cm[6*NH+o] = aSxz[j];
        g_cm[7*NH+o] = aSyy[j]; g_cm[8*NH+o] = aSyz[j]; g_cm[9*NH+o] = aSzz[j];
    }
}

// ---------------- tf32 tensor-core GEMM (3xTF32 split, fp32-grade accuracy) ----------------
template<int ACT>
__device__ __forceinline__ void gemm_core(const float* __restrict__ A, const float* __restrict__ W,
                                          const float* __restrict__ bias, float* __restrict__ C,
                                          int K, int O) {
    __shared__ __align__(16) float As[32*132];
    __shared__ __align__(16) float Ws[32*68];
    int tid = threadIdx.x;
    int w = tid >> 5, lane = tid & 31;
    int gid = lane >> 2, tig = lane & 3;
    int mw = (w & 3) * 32, nw = (w >> 2) * 32;
    int rowBase = blockIdx.y * 128;
    int colBase = blockIdx.x * 64;

    float acc[2][4][4];
    #pragma unroll
    for (int mi = 0; mi < 2; mi++)
        #pragma unroll
        for (int ni = 0; ni < 4; ni++)
            #pragma unroll
            for (int q = 0; q < 4; q++) acc[mi][ni][q] = 0.f;

    for (int k0 = 0; k0 < K; k0 += 32) {
        #pragma unroll
        for (int i = 0; i < 16; i++) {
            int lin = tid + i*256;
            int m = lin >> 5, k = lin & 31;
            As[k*132 + m] = A[(size_t)(rowBase + m)*K + k0 + k];
        }
        #pragma unroll
        for (int i = 0; i < 8; i++) {
            int lin = tid + i*256;
            int n = lin >> 5, k = lin & 31;
            Ws[k*68 + n] = W[(size_t)(colBase + n)*K + k0 + k];
        }
        __syncthreads();

        #pragma unroll
        for (int s = 0; s < 4; s++) {
            int kk = s * 8;
            unsigned ah[2][4], al[2][4];
            #pragma unroll
            for (int mi = 0; mi < 2; mi++) {
                int mb = mw + mi*16 + gid;
                float a0 = As[(kk+tig)*132   + mb];
                float a1 = As[(kk+tig)*132   + mb + 8];
                float a2 = As[(kk+tig+4)*132 + mb];
                float a3 = As[(kk+tig+4)*132 + mb + 8];
                tf32split(a0, ah[mi][0], al[mi][0]);
                tf32split(a1, ah[mi][1], al[mi][1]);
                tf32split(a2, ah[mi][2], al[mi][2]);
                tf32split(a3, ah[mi][3], al[mi][3]);
            }
            unsigned bh[4][2], bl[4][2];
            #pragma unroll
            for (int ni = 0; ni < 4; ni++) {
                int nb = nw + ni*8 + gid;
                float b0 = Ws[(kk+tig)*68   + nb];
                float b1 = Ws[(kk+tig+4)*68 + nb];
                tf32split(b0, bh[ni][0], bl[ni][0]);
                tf32split(b1, bh[ni][1], bl[ni][1]);
            }
            #pragma unroll
            for (int mi = 0; mi < 2; mi++)
                #pragma unroll
                for (int ni = 0; ni < 4; ni++) {
                    mma_tf32(acc[mi][ni], ah[mi], bh[ni]);
                    mma_tf32(acc[mi][ni], al[mi], bh[ni]);
                    mma_tf32(acc[mi][ni], ah[mi], bl[ni]);
                }
        }
        __syncthreads();
    }

    #pragma unroll
    for (int mi = 0; mi < 2; mi++)
        #pragma unroll
        for (int ni = 0; ni < 4; ni++) {
            int r0 = rowBase + mw + mi*16 + gid;
            int c0 = colBase + nw + ni*8 + tig*2;
            float d0 = acc[mi][ni][0], d1 = acc[mi][ni][1];
            float d2 = acc[mi][ni][2], d3 = acc[mi][ni][3];
            if (bias) {
                float bb0 = __ldg(&bias[c0]), bb1 = __ldg(&bias[c0+1]);
                d0 += bb0; d1 += bb1; d2 += bb0; d3 += bb1;
            }
            if (ACT) {
                d0 = d0 / (1.0f + __expf(-d0));
                d1 = d1 / (1.0f + __expf(-d1));
                d2 = d2 / (1.0f + __expf(-d2));
                d3 = d3 / (1.0f + __expf(-d3));
            }
            *(float2*)&C[(size_t)r0*O + c0]     = make_float2(d0, d1);
            *(float2*)&C[(size_t)(r0+8)*O + c0] = make_float2(d2, d3);
        }
}

template<int ACT>
__global__ void k_gemm(int aId, const float* __restrict__ W,
                       const float* __restrict__ bias, int cId,
                       int K, int O) {
    gemm_core<ACT>(gptr(aId), W, bias, gptr(cId), K, O);
}

__global__ void k_gemm_mix(const float* __restrict__ lt0, const float* __restrict__ lt1,
                           const float* __restrict__ lt2) {
    int c = blockIdx.z;
    const float* A = g_cm + (size_t)c*NH;
    const float* W = (c == 0) ? lt0 : (c < 4 ? lt1 : lt2);
    float* C = g_mix + (size_t)c*NH;
    gemm_core<0>(A, W, nullptr, C, HH, HH);
}

// ---------------- fused combine (norms*gates^2) + LayerNorm(3H=384) ----------------
__global__ void __launch_bounds__(128) k_combine_outln(const float* __restrict__ og,
                                                       const float* __restrict__ ob) {
    __shared__ float sred[8];
    int n = blockIdx.x;
    int h = threadIdx.x;                  // 0..127
    size_t idx = (size_t)n*HH + h;
    float mi  = g_mix[0*NH+idx];
    float ax  = g_mix[1*NH+idx], ay = g_mix[2*NH+idx], az = g_mix[3*NH+idx];
    float sxx = g_mix[4*NH+idx], sxy = g_mix[5*NH+idx], sxz = g_mix[6*NH+idx];
    float syy = g_mix[7*NH+idx], syz = g_mix[8*NH+idx], szz = g_mix[9*NH+idx];
    float s0 = g_scal[n*384 + 3*h + 0];
    float s1 = g_scal[n*384 + 3*h + 1];
    float s2 = g_scal[n*384 + 3*h + 2];
    float xI = 3.f*mi*mi*s0*s0;
    float xA = 2.f*(ax*ax + ay*ay + az*az)*s1*s1;
    float xS = (sxx*sxx + syy*syy + szz*szz
                + 2.f*(sxy*sxy + sxz*sxz + syz*syz))*s2*s2;

    int lane = h & 31, w = h >> 5;
    float s = warp_sum(xI + xA + xS);
    if (lane == 0) sred[w] = s;
    __syncthreads();
    float mu = (sred[0]+sred[1]+sred[2]+sred[3]) * (1.0f/384.0f);
    float dI = xI-mu, dA = xA-mu, dS = xS-mu;
    float v = warp_sum(dI*dI + dA*dA + dS*dS);
    if (lane == 0) sred[4 + w] = v;
    __syncthreads();
    float var = (sred[4]+sred[5]+sred[6]+sred[7]) * (1.0f/384.0f);
    float rs = rsqrtf(var + 1e-5f);
    g_xln[(size_t)n*384 + h]       = dI*rs*__ldg(&og[h])       + __ldg(&ob[h]);
    g_xln[(size_t)n*384 + 128 + h] = dA*rs*__ldg(&og[128 + h]) + __ldg(&ob[128 + h]);
    g_xln[(size_t)n*384 + 256 + h] = dS*rs*__ldg(&og[256 + h]) + __ldg(&ob[256 + h]);
}

// ---------------- final per-atom dot: out[n] = silu(s2)·ol2_w + b ----------------
__global__ void k_final(const float* __restrict__ ol2w, const float* __restrict__ ol2b,
                        float* __restrict__ out) {
    int a = (blockIdx.x * blockDim.x + threadIdx.x) >> 5;
    if (a >= NN) return;
    int lane = threadIdx.x & 31;
    float v = g_s2[a*64 + lane]      * __ldg(&ol2w[lane])
            + g_s2[a*64 + lane + 32] * __ldg(&ol2w[lane + 32]);
    v = warp_sum(v);
    if (lane == 0) out[a] = v + ol2b[0];
}

// ---------------- launch: forked graph (side streams joined via events) ----------------
extern "C" void kernel_launch(void* const* d_in, const int* in_sizes, int n_in,
                              void* d_out, int out_size) {
    const float* edge_vec = (const float*)d_in[0];
    const float* emb_w    = (const float*)d_in[1];
    const float* emb2_w   = (const float*)d_in[2];
    const float* emb2_b   = (const float*)d_in[3];
    const float* dp1_w    = (const float*)d_in[4];
    const float* dp1_b    = (const float*)d_in[5];
    const float* dp2_w    = (const float*)d_in[6];
    const float* dp2_b    = (const float*)d_in[7];
    const float* dp3_w    = (const float*)d_in[8];
    const float* dp3_b    = (const float*)d_in[9];
    const float* lt0_w    = (const float*)d_in[10];
    const float* lt1_w    = (const float*)d_in[11];
    const float* lt2_w    = (const float*)d_in[12];
    const float* ls0_w    = (const float*)d_in[13];
    const float* ls0_b    = (const float*)d_in[14];
    const float* ls1_w    = (const float*)d_in[15];
    const float* ls1_b    = (const float*)d_in[16];
    const float* init_g   = (const float*)d_in[17];
    const float* init_b   = (const float*)d_in[18];
    const float* lin_w    = (const float*)d_in[19];
    const float* lin_b    = (const float*)d_in[20];
    const float* outn_g   = (const float*)d_in[21];
    const float* outn_b   = (const float*)d_in[22];
    const float* ol1_w    = (const float*)d_in[23];
    const float* ol1_b    = (const float*)d_in[24];
    const float* ol2_w    = (const float*)d_in[25];
    const float* ol2_b    = (const float*)d_in[26];
    const int*   z        = (const int*)d_in[27];
    const int*   eidx     = (const int*)d_in[28];
    float* out = (float*)d_out;

    float m0   = expf(-4.5f);                 // first RBF mean (exp(-cutoff))
    float dm   = (1.0f - m0) / 31.0f;
    float tmp  = (2.0f/32.0f) * (1.0f - m0);
    float beta = 1.0f / (tmp*tmp);
    float x0   = expf(-5.0f);                 // min of x=exp(-alpha*d) for d<4.5
    float dstep = (1.0f - x0) / (float)(NB - 1);
    float invD  = 1.0f / dstep;

    cudaStream_t sA, sB;
    cudaStreamCreateWithFlags(&sA, cudaStreamNonBlocking);
    cudaStreamCreateWithFlags(&sB, cudaStreamNonBlocking);
    cudaEvent_t eF1, eJ1, eF2, eJ2;
    cudaEventCreateWithFlags(&eF1, cudaEventDisableTiming);
    cudaEventCreateWithFlags(&eJ1, cudaEventDisableTiming);
    cudaEventCreateWithFlags(&eF2, cudaEventDisableTiming);
    cudaEventCreateWithFlags(&eJ2, cudaEventDisableTiming);

    // ---- fork 1: weight-table branch (sA) ∥ edge-sort branch (main) ----
    cudaEventRecord(eF1, 0);
    cudaStreamWaitEvent(sA, eF1, 0);
    k_tables<<<128, 128, 0, sA>>>(emb_w, emb2_w, emb2_b);
    k_btab<<<NB/8, 128, 0, sA>>>(dp1_w, dp2_w, dp3_w, m0, dm, beta, x0, dstep);
    cudaEventRecord(eJ1, sA);

    k_hist<<<EE/256, 256>>>(eidx);
    k_scan<<<1, 1024>>>();
    k_scatter<<<EE/256, 256>>>(eidx, edge_vec, z, x0, invD);
    cudaStreamWaitEvent(0, eJ1, 0);           // join tables/btab before gather

    // ---- gather (critical path): 2 warps/atom, prefetched ----
    k_gather<<<NN/2, 128>>>(dp1_b, dp2_b, dp3_b, z, init_g, init_b);

    // ---- fork 2: mix GEMM (sB, reads g_cm) ∥ gating MLP (main, reads g_nrm) ----
    cudaEventRecord(eF2, 0);
    cudaStreamWaitEvent(sB, eF2, 0);
    k_gemm_mix<<<dim3(128/64, NN/128, 10), 256, 0, sB>>>(lt0_w, lt1_w, lt2_w);
    cudaEventRecord(eJ2, sB);

    k_gemm<1><<<dim3(256/64, NN/128), 256>>>(0, ls0_w, ls0_b, 1, 128, 256);
    k_gemm<1><<<dim3(384/64, NN/128), 256>>>(1, ls1_w, ls1_b, 2, 256, 384);
    cudaStreamWaitEvent(0, eJ2, 0);           // join mix before combine

    // ---- combine + LN(3H), output MLP ----
    k_combine_outln<<<NN, 128>>>(outn_g, outn_b);
    k_gemm<1><<<dim3(128/64, NN/128), 256>>>(3, lin_w, lin_b, 4, 384, 128);
    k_gemm<1><<<dim3(64/64,  NN/128), 256>>>(4, ol1_w, ol1_b, 5, 128, 64);
    k_final<<<NN/8, 256>>>(ol2_w, ol2_b, out);

    // Destroy only when not capturing (destroying a capturing stream is illegal;
    // during the single capture call we intentionally leak 2 streams + 4 events).
    cudaStreamCaptureStatus cs = cudaStreamCaptureStatusNone;
    cudaStreamIsCapturing(0, &cs);
    if (cs == cudaStreamCaptureStatusNone) {
        cudaStreamDestroy(sA);
        cudaStreamDestroy(sB);
        cudaEventDestroy(eF1);
        cudaEventDestroy(eJ1);
        cudaEventDestroy(eF2);
        cudaEventDestroy(eJ2);
    }
}

// round 17
// speedup vs baseline: 1.0555x; 1.0555x over previous
#include <cuda_runtime.h>
#include <cuda_bf16.h>
#include <cuda_fp16.h>
#include <math.h>

#define NN 4096
#define EE 65536
#define HH 128
#define RR 32
#define NB 2048
#define NH (NN*HH)

// ---------------- scratch (device globals; no runtime allocation) ----------------
__device__ __align__(16) float g_cm[10*NH];     // comp-major tensor components for mix GEMM
__device__ __align__(16) float g_T1[128*HH];
__device__ __align__(16) float g_T2[128*HH];
__device__ __align__(16) float4 g_tab4[NB*HH];  // fp32 staging: per x-node, per h: (dot1,dot2,dot3,-)
__device__ __align__(16) uint4  g_tabP[NB*HH];  // packed: half2(v@bin, v@bin+1) per channel
__device__ __align__(16) float g_nrm[NH];
__device__ __align__(16) float g_h[NN*256];
__device__ __align__(16) float g_scal[NN*384];
__device__ __align__(16) float g_mix[10*NH];
__device__ __align__(16) float g_xln[NN*384];
__device__ __align__(16) float g_s1[NN*HH];
// counting-sort scratch. g_cnt is zero at module load; k_scan re-zeroes it
// after reading, so every kernel_launch call (and graph replay) sees zeros.
__device__ int g_cnt[NN];
__device__ int g_off[NN+1];
__device__ int g_pos[NN];
// pre-sorted per-edge payload: {ux,uy,uz,cut} and {u(table coord), zt}
__device__ __align__(16) float4 g_pay1[EE];
__device__ __align__(16) float2 g_pay2[EE];

// Device-side resolution of scratch buffers (host must never pass __device__ globals).
__device__ __forceinline__ float* gptr(int id) {
    switch (id) {
        case 0: return g_nrm;
        case 1: return g_h;
        case 2: return g_scal;
        case 3: return g_xln;
        case 4: return g_s1;
    }
    return nullptr;
}

__device__ __forceinline__ float warp_sum(float v) {
    #pragma unroll
    for (int o = 16; o > 0; o >>= 1) v += __shfl_xor_sync(0xffffffffu, v, o);
    return v;
}

// ---------------- tf32 helpers ----------------
__device__ __forceinline__ void tf32split(float x, unsigned &hi, unsigned &lo) {
    unsigned h;
    asm("cvt.rna.tf32.f32 %0, %1;" : "=r"(h) : "f"(x));
    float r = x - __uint_as_float(h);
    unsigned l;
    asm("cvt.rna.tf32.f32 %0, %1;" : "=r"(l) : "f"(r));
    hi = h; lo = l;
}

__device__ __forceinline__ void mma_tf32(float* d, const unsigned* a, const unsigned* b) {
    asm volatile(
        "mma.sync.aligned.m16n8k8.row.col.f32.tf32.tf32.f32 "
        "{%0,%1,%2,%3}, {%4,%5,%6,%7}, {%8,%9}, {%0,%1,%2,%3};\n"
        : "+f"(d[0]), "+f"(d[1]), "+f"(d[2]), "+f"(d[3])
        : "r"(a[0]), "r"(a[1]), "r"(a[2]), "r"(a[3]), "r"(b[0]), "r"(b[1]));
}

// ---------------- T1/T2 tables: fold emb + emb2 (+bias) over the 128 atom types ----------------
__global__ void k_tables(const float* __restrict__ emb_w, const float* __restrict__ emb2_w,
                         const float* __restrict__ emb2_b) {
    int t = blockIdx.x;          // atom type 0..127
    int h = threadIdx.x;         // 0..127
    __shared__ float se[128];
    se[h] = emb_w[t*HH + h];
    __syncthreads();
    float s1 = emb2_b[h], s2 = 0.f;
    #pragma unroll 8
    for (int k = 0; k < 128; k++) {
        s1 = fmaf(emb2_w[h*256 + k],       se[k], s1);
        s2 = fmaf(emb2_w[h*256 + 128 + k], se[k], s2);
    }
    g_T1[t*HH + h] = s1;
    g_T2[t*HH + h] = s2;
}

// ---------------- RBF->dp matvec lookup table over x = exp(-alpha*d) ----------------
__global__ void k_btab(const float* __restrict__ dp1w, const float* __restrict__ dp2w,
                       const float* __restrict__ dp3w,
                       float m0, float dm, float beta, float x0, float dstep) {
    __shared__ float srb[8*32];
    int h  = threadIdx.x;          // 0..127
    int b0 = blockIdx.x * 8;       // 8 nodes per block
    for (int k = h; k < 8*32; k += 128) {
        int bin = k >> 5, r = k & 31;
        float xr = x0 + (float)(b0 + bin) * dstep;
        float df = xr - (m0 + dm * (float)r);
        srb[k] = __expf(-beta * df * df);
    }
    __syncthreads();
    const float4* p1 = (const float4*)(dp1w + h*RR);
    const float4* p2 = (const float4*)(dp2w + h*RR);
    const float4* p3 = (const float4*)(dp3w + h*RR);
    #pragma unroll
    for (int bin = 0; bin < 8; bin++) {
        float v1 = 0.f, v2 = 0.f, v3 = 0.f;
        #pragma unroll
        for (int q = 0; q < 8; q++) {
            float4 f1 = __ldg(&p1[q]);
            float4 f2 = __ldg(&p2[q]);
            float4 f3 = __ldg(&p3[q]);
            const float* sb = &srb[bin*32 + q*4];
            v1 = fmaf(f1.x, sb[0], fmaf(f1.y, sb[1], fmaf(f1.z, sb[2], fmaf(f1.w, sb[3], v1))));
            v2 = fmaf(f2.x, sb[0], fmaf(f2.y, sb[1], fmaf(f2.z, sb[2], fmaf(f2.w, sb[3], v2))));
            v3 = fmaf(f3.x, sb[0], fmaf(f3.y, sb[1], fmaf(f3.z, sb[2], fmaf(f3.w, sb[3], v3))));
        }
        g_tab4[(size_t)(b0 + bin)*HH + h] = make_float4(v1, v2, v3, 0.f);
    }
}

// ---------------- pack lerp endpoints: tabP[bin][h] = half2(v@bin, v@bin+1) x3 ----------------
__global__ void k_pack() {
    int bin = blockIdx.x;
    int h   = threadIdx.x;
    int b2  = (bin + 1 < NB) ? bin + 1 : bin;
    float4 lo = g_tab4[(size_t)bin*HH + h];
    float4 hi = g_tab4[(size_t)b2*HH + h];
    __half2 c1 = __floats2half2_rn(lo.x, hi.x);
    __half2 c2 = __floats2half2_rn(lo.y, hi.y);
    __half2 c3 = __floats2half2_rn(lo.z, hi.z);
    uint4 o;
    o.x = *reinterpret_cast<unsigned*>(&c1);
    o.y = *reinterpret_cast<unsigned*>(&c2);
    o.z = *reinterpret_cast<unsigned*>(&c3);
    o.w = 0u;
    g_tabP[(size_t)bin*HH + h] = o;
}

// ---------------- counting sort: histogram ----------------
__global__ void k_hist(const int* __restrict__ eidx) {
    int e = blockIdx.x * blockDim.x + threadIdx.x;
    if (e < EE) atomicAdd(&g_cnt[eidx[e]], 1);
}

// ---------------- scan only (single 1024-thread block over 4096 counters) ----------------
__global__ void k_scan() {
    __shared__ int ssum[32];
    int t = threadIdx.x, lane = t & 31, w = t >> 5;
    int c0 = g_cnt[t*4+0], c1 = g_cnt[t*4+1], c2 = g_cnt[t*4+2], c3 = g_cnt[t*4+3];
    g_cnt[t*4+0] = 0; g_cnt[t*4+1] = 0; g_cnt[t*4+2] = 0; g_cnt[t*4+3] = 0;
    int tot = c0 + c1 + c2 + c3;
    int inc = tot;
    #pragma unroll
    for (int o = 1; o < 32; o <<= 1) {
        int v = __shfl_up_sync(0xffffffffu, inc, o);
        if (lane >= o) inc += v;
    }
    if (lane == 31) ssum[w] = inc;
    __syncthreads();
    if (w == 0) {
        int i2 = ssum[lane];
        #pragma unroll
        for (int o = 1; o < 32; o <<= 1) {
            int u = __shfl_up_sync(0xffffffffu, i2, o);
            if (lane >= o) i2 += u;
        }
        ssum[lane] = i2;
    }
    __syncthreads();
    int base = (w ? ssum[w-1] : 0) + inc - tot;       // exclusive prefix
    int o0 = base, o1 = base + c0, o2 = o1 + c1, o3 = o2 + c2;
    g_off[t*4+0] = o0; g_off[t*4+1] = o1; g_off[t*4+2] = o2; g_off[t*4+3] = o3;
    g_pos[t*4+0] = o0; g_pos[t*4+1] = o1; g_pos[t*4+2] = o2; g_pos[t*4+3] = o3;
    if (t == 1023) g_off[NN] = o3 + c3;
}

// ---------------- scatter: per-edge prologue computed here, written to sorted slot ----------------
__global__ void k_scatter(const int* __restrict__ eidx, const float* __restrict__ edge_vec,
                          const int* __restrict__ z, float x0, float invD) {
    const float PI_CU = 3.14159265358979f / 4.5f;
    const float ALPHA = 5.0f / 4.5f;
    int e = blockIdx.x * blockDim.x + threadIdx.x;
    if (e >= EE) return;
    int s = __ldg(&eidx[e]);
    int slot = atomicAdd(&g_pos[s], 1);
    float ex = __ldg(&edge_vec[e*3+0]);
    float ey = __ldg(&edge_vec[e*3+1]);
    float ez = __ldg(&edge_vec[e*3+2]);
    float d  = sqrtf(ex*ex + ey*ey + ez*ez);
    float inv = 1.0f / d;
    float cut = (d < 4.5f) ? 0.5f*(cosf(PI_CU*d) + 1.0f) : 0.0f;
    float u   = (__expf(-ALPHA*d) - x0) * invD;
    int zt = __ldg(&z[__ldg(&eidx[EE + e])]);
    g_pay1[slot] = make_float4(ex*inv, ey*inv, ez*inv, cut);
    g_pay2[slot] = make_float2(u, __int_as_float(zt));
}

// ---------------- gather: 2 warps per atom, packed fp16 table lerp ----------------
__global__ void __launch_bounds__(128) k_gather(
    const float* __restrict__ dp1b, const float* __restrict__ dp2b,
    const float* __restrict__ dp3b, const int* __restrict__ z,
    const float* __restrict__ ig, const float* __restrict__ ib)
{
    __shared__ float sacc[2][10][4][32];     // [atomInBlk][comp][j][lane]
    int tid  = threadIdx.x;
    int lane = tid & 31, w = tid >> 5;
    int aib  = w >> 1;                       // atom within block (0..1)
    int sub  = w & 1;                        // warp half (0/1)
    int n = blockIdx.x * 2 + aib;
    int off0 = g_off[n];
    int endE = g_off[n+1];
    int zn   = __ldg(&z[n]);

    float t1h[4], b1h[4], b2h[4], b3h[4];
    #pragma unroll
    for (int j = 0; j < 4; j++) {
        int h = lane + 32*j;
        t1h[j] = g_T1[zn*HH + h];
        b1h[j] = __ldg(&dp1b[h]);
        b2h[j] = __ldg(&dp2b[h]);
        b3h[j] = __ldg(&dp3b[h]);
    }

    float aI[4], aAx[4], aAy[4], aAz[4];
    float aSxx[4], aSxy[4], aSxz[4], aSyy[4], aSyz[4], aSzz[4];
    #pragma unroll
    for (int j = 0; j < 4; j++) {
        aI[j]=0.f; aAx[j]=0.f; aAy[j]=0.f; aAz[j]=0.f;
        aSxx[j]=0.f; aSxy[j]=0.f; aSxz[j]=0.f; aSyy[j]=0.f; aSyz[j]=0.f; aSzz[j]=0.f;
    }

    // stride-2 interleaved split across the warp pair, payload double-buffered
    int i = off0 + sub;
    float4 nf1 = make_float4(0.f,0.f,0.f,0.f);
    float2 nf2 = make_float2(0.f,0.f);
    if (i < endE) { nf1 = __ldg(&g_pay1[i]); nf2 = __ldg(&g_pay2[i]); }
    for (; i < endE; i += 2) {
        float4 p1 = nf1;
        float2 p2 = nf2;
        int nx = i + 2;
        if (nx < endE) { nf1 = __ldg(&g_pay1[nx]); nf2 = __ldg(&g_pay2[nx]); }

        float cut = p1.w;
        if (cut == 0.0f) continue;
        float u = p2.x;
        int bin = (int)u;
        bin = (bin < 0) ? 0 : ((bin > NB-2) ? NB-2 : bin);
        float frac = u - (float)bin;
        int zt = __float_as_int(p2.y);

        float x = p1.x, y = p1.y, zc = p1.z;
        float tr3 = (x*x + y*y + zc*zc) * (1.0f/3.0f);
        float oxx = x*x - tr3, oyy = y*y - tr3, ozz = zc*zc - tr3;
        float oxy = x*y, oxz = x*zc, oyz = y*zc;

        const uint4* rowP = g_tabP + (size_t)bin*HH;
        const float* t2r  = g_T2 + zt*HH;

        #pragma unroll
        for (int j = 0; j < 4; j++) {
            int h = lane + 32*j;
            uint4 tw = __ldg(&rowP[h]);
            float t2 = __ldg(&t2r[h]);
            float2 c1 = __half22float2(*reinterpret_cast<__half2*>(&tw.x));
            float2 c2 = __half22float2(*reinterpret_cast<__half2*>(&tw.y));
            float2 c3 = __half22float2(*reinterpret_cast<__half2*>(&tw.z));
            float dot1 = fmaf(frac, c1.y - c1.x, c1.x);
            float dot2 = fmaf(frac, c2.y - c2.x, c2.x);
            float dot3 = fmaf(frac, c3.y - c3.x, c3.x);
            float c   = cut * (t1h[j] + t2);
            float w1 = fmaf(cut, dot1, b1h[j]) * c;
            float w2 = fmaf(cut, dot2, b2h[j]) * c;
            float w3 = fmaf(cut, dot3, b3h[j]) * c;
            aI[j]  += w1;
            aAx[j]  = fmaf(w2, x,  aAx[j]);
            aAy[j]  = fmaf(w2, y,  aAy[j]);
            aAz[j]  = fmaf(w2, zc, aAz[j]);
            aSxx[j] = fmaf(w3, oxx, aSxx[j]);
            aSyy[j] = fmaf(w3, oyy, aSyy[j]);
            aSzz[j] = fmaf(w3, ozz, aSzz[j]);
            aSxy[j] = fmaf(w3, oxy, aSxy[j]);
            aSxz[j] = fmaf(w3, oxz, aSxz[j]);
            aSyz[j] = fmaf(w3, oyz, aSyz[j]);
        }
    }

    // merge the odd warp's partials into the even warp via smem
    if (sub == 1) {
        #pragma unroll
        for (int j = 0; j < 4; j++) {
            sacc[aib][0][j][lane] = aI[j];
            sacc[aib][1][j][lane] = aAx[j];
            sacc[aib][2][j][lane] = aAy[j];
            sacc[aib][3][j][lane] = aAz[j];
            sacc[aib][4][j][lane] = aSxx[j];
            sacc[aib][5][j][lane] = aSxy[j];
            sacc[aib][6][j][lane] = aSxz[j];
            sacc[aib][7][j][lane] = aSyy[j];
            sacc[aib][8][j][lane] = aSyz[j];
            sacc[aib][9][j][lane] = aSzz[j];
        }
    }
    __syncthreads();
    if (sub == 1) return;

    #pragma unroll
    for (int j = 0; j < 4; j++) {
        aI[j]   += sacc[aib][0][j][lane];
        aAx[j]  += sacc[aib][1][j][lane];
        aAy[j]  += sacc[aib][2][j][lane];
        aAz[j]  += sacc[aib][3][j][lane];
        aSxx[j] += sacc[aib][4][j][lane];
        aSxy[j] += sacc[aib][5][j][lane];
        aSxz[j] += sacc[aib][6][j][lane];
        aSyy[j] += sacc[aib][7][j][lane];
        aSyz[j] += sacc[aib][8][j][lane];
        aSzz[j] += sacc[aib][9][j][lane];
    }

    float tn[4];
    #pragma unroll
    for (int j = 0; j < 4; j++) {
        tn[j] = 3.f*aI[j]*aI[j]
              + 2.f*(aAx[j]*aAx[j] + aAy[j]*aAy[j] + aAz[j]*aAz[j])
              + aSxx[j]*aSxx[j] + aSyy[j]*aSyy[j] + aSzz[j]*aSzz[j]
              + 2.f*(aSxy[j]*aSxy[j] + aSxz[j]*aSxz[j] + aSyz[j]*aSyz[j]);
    }
    float s  = warp_sum(tn[0] + tn[1] + tn[2] + tn[3]);
    float mu = s * (1.0f/128.0f);
    float v = 0.f;
    #pragma unroll
    for (int j = 0; j < 4; j++) { float d = tn[j]-mu; v += d*d; }
    v = warp_sum(v) * (1.0f/128.0f);
    float rs = rsqrtf(v + 1e-5f);

    #pragma unroll
    for (int j = 0; j < 4; j++) {
        int h = lane + 32*j;
        size_t o = (size_t)n*HH + h;
        g_nrm[o] = (tn[j]-mu)*rs*__ldg(&ig[h]) + __ldg(&ib[h]);
        g_cm[0*NH+o] = aI[j];
        g_cm[1*NH+o] = aAx[j];  g_cm[2*NH+o] = aAy[j];  g_cm[3*NH+o] = aAz[j];
        g_cm[4*NH+o] = aSxx[j]; g_cm[5*NH+o] = aSxy[j]; g_cm[6*NH+o] = aSxz[j];
        g_cm[7*NH+o] = aSyy[j]; g_cm[8*NH+o] = aSyz[j]; g_cm[9*NH+o] = aSzz[j];
    }
}

// ---------------- tf32 tensor-core GEMM (3xTF32 split, fp32-grade accuracy) ----------------
template<int ACT>
__device__ __forceinline__ void gemm_core(const float* __restrict__ A, const float* __restrict__ W,
                                          const float* __restrict__ bias, float* __restrict__ C,
                                          int K, int O) {
    __shared__ __align__(16) float As[32*132];
    __shared__ __align__(16) float Ws[32*68];
    int tid = threadIdx.x;
    int w = tid >> 5, lane = tid & 31;
    int gid = lane >> 2, tig = lane & 3;
    int mw = (w & 3) * 32, nw = (w >> 2) * 32;
    int rowBase = blockIdx.y * 128;
    int colBase = blockIdx.x * 64;

    float acc[2][4][4];
    #pragma unroll
    for (int mi = 0; mi < 2; mi++)
        #pragma unroll
        for (int ni = 0; ni < 4; ni++)
            #pragma unroll
            for (int q = 0; q < 4; q++) acc[mi][ni][q] = 0.f;

    for (int k0 = 0; k0 < K; k0 += 32) {
        #pragma unroll
        for (int i = 0; i < 16; i++) {
            int lin = tid + i*256;
            int m = lin >> 5, k = lin & 31;
            As[k*132 + m] = A[(size_t)(rowBase + m)*K + k0 + k];
        }
        #pragma unroll
        for (int i = 0; i < 8; i++) {
            int lin = tid + i*256;
            int n = lin >> 5, k = lin & 31;
            Ws[k*68 + n] = W[(size_t)(colBase + n)*K + k0 + k];
        }
        __syncthreads();

        #pragma unroll
        for (int s = 0; s < 4; s++) {
            int kk = s * 8;
            unsigned ah[2][4], al[2][4];
            #pragma unroll
            for (int mi = 0; mi < 2; mi++) {
                int mb = mw + mi*16 + gid;
                float a0 = As[(kk+tig)*132   + mb];
                float a1 = As[(kk+tig)*132   + mb + 8];
                float a2 = As[(kk+tig+4)*132 + mb];
                float a3 = As[(kk+tig+4)*132 + mb + 8];
                tf32split(a0, ah[mi][0], al[mi][0]);
                tf32split(a1, ah[mi][1], al[mi][1]);
                tf32split(a2, ah[mi][2], al[mi][2]);
                tf32split(a3, ah[mi][3], al[mi][3]);
            }
            unsigned bh[4][2], bl[4][2];
            #pragma unroll
            for (int ni = 0; ni < 4; ni++) {
                int nb = nw + ni*8 + gid;
                float b0 = Ws[(kk+tig)*68   + nb];
                float b1 = Ws[(kk+tig+4)*68 + nb];
                tf32split(b0, bh[ni][0], bl[ni][0]);
                tf32split(b1, bh[ni][1], bl[ni][1]);
            }
            #pragma unroll
            for (int mi = 0; mi < 2; mi++)
                #pragma unroll
                for (int ni = 0; ni < 4; ni++) {
                    mma_tf32(acc[mi][ni], ah[mi], bh[ni]);
                    mma_tf32(acc[mi][ni], al[mi], bh[ni]);
                    mma_tf32(acc[mi][ni], ah[mi], bl[ni]);
                }
        }
        __syncthreads();
    }

    #pragma unroll
    for (int mi = 0; mi < 2; mi++)
        #pragma unroll
        for (int ni = 0; ni < 4; ni++) {
            int r0 = rowBase + mw + mi*16 + gid;
            int c0 = colBase + nw + ni*8 + tig*2;
            float d0 = acc[mi][ni][0], d1 = acc[mi][ni][1];
            float d2 = acc[mi][ni][2], d3 = acc[mi][ni][3];
            if (bias) {
                float bb0 = __ldg(&bias[c0]), bb1 = __ldg(&bias[c0+1]);
                d0 += bb0; d1 += bb1; d2 += bb0; d3 += bb1;
            }
            if (ACT) {
                d0 = d0 / (1.0f + __expf(-d0));
                d1 = d1 / (1.0f + __expf(-d1));
                d2 = d2 / (1.0f + __expf(-d2));
                d3 = d3 / (1.0f + __expf(-d3));
            }
            *(float2*)&C[(size_t)r0*O + c0]     = make_float2(d0, d1);
            *(float2*)&C[(size_t)(r0+8)*O + c0] = make_float2(d2, d3);
        }
}

template<int ACT>
__global__ void k_gemm(int aId, const float* __restrict__ W,
                       const float* __restrict__ bias, int cId,
                       int K, int O) {
    gemm_core<ACT>(gptr(aId), W, bias, gptr(cId), K, O);
}

__global__ void k_gemm_mix(const float* __restrict__ lt0, const float* __restrict__ lt1,
                           const float* __restrict__ lt2) {
    int c = blockIdx.z;
    const float* A = g_cm + (size_t)c*NH;
    const float* W = (c == 0) ? lt0 : (c < 4 ? lt1 : lt2);
    float* C = g_mix + (size_t)c*NH;
    gemm_core<0>(A, W, nullptr, C, HH, HH);
}

// ---------------- last GEMM (128->64, silu) fused with the final ol2 dot ----------------
// out[n] = silu(s1[n]·ol1 + b)·ol2_w + ol2_b.  Tile 128 rows x 64 cols (full O).
__global__ void __launch_bounds__(256) k_gemm_last(const float* __restrict__ W,
                                                   const float* __restrict__ bias,
                                                   const float* __restrict__ ol2w,
                                                   const float* __restrict__ ol2b,
                                                   float* __restrict__ out) {
    const int K = 128, O = 64;
    const float* A = g_s1;
    __shared__ __align__(16) float As[32*132];
    __shared__ __align__(16) float Ws[32*68];
    __shared__ float sout[128][2];
    int tid = threadIdx.x;
    int w = tid >> 5, lane = tid & 31;
    int gid = lane >> 2, tig = lane & 3;
    int mw = (w & 3) * 32, nw = (w >> 2) * 32;
    int rowBase = blockIdx.y * 128;

    float acc[2][4][4];
    #pragma unroll
    for (int mi = 0; mi < 2; mi++)
        #pragma unroll
        for (int ni = 0; ni < 4; ni++)
            #pragma unroll
            for (int q = 0; q < 4; q++) acc[mi][ni][q] = 0.f;

    for (int k0 = 0; k0 < K; k0 += 32) {
        #pragma unroll
        for (int i = 0; i < 16; i++) {
            int lin = tid + i*256;
            int m = lin >> 5, k = lin & 31;
            As[k*132 + m] = A[(size_t)(rowBase + m)*K + k0 + k];
        }
        #pragma unroll
        for (int i = 0; i < 8; i++) {
            int lin = tid + i*256;
            int n = lin >> 5, k = lin & 31;
            Ws[k*68 + n] = W[(size_t)n*K + k0 + k];
        }
        __syncthreads();
        #pragma unroll
        for (int s = 0; s < 4; s++) {
            int kk = s * 8;
            unsigned ah[2][4], al[2][4];
            #pragma unroll
            for (int mi = 0; mi < 2; mi++) {
                int mb = mw + mi*16 + gid;
                float a0 = As[(kk+tig)*132   + mb];
                float a1 = As[(kk+tig)*132   + mb + 8];
                float a2 = As[(kk+tig+4)*132 + mb];
                float a3 = As[(kk+tig+4)*132 + mb + 8];
                tf32split(a0, ah[mi][0], al[mi][0]);
                tf32split(a1, ah[mi][1], al[mi][1]);
                tf32split(a2, ah[mi][2], al[mi][2]);
                tf32split(a3, ah[mi][3], al[mi][3]);
            }
            unsigned bh[4][2], bl[4][2];
            #pragma unroll
            for (int ni = 0; ni < 4; ni++) {
                int nb = nw + ni*8 + gid;
                float b0 = Ws[(kk+tig)*68   + nb];
                float b1 = Ws[(kk+tig+4)*68 + nb];
                tf32split(b0, bh[ni][0], bl[ni][0]);
                tf32split(b1, bh[ni][1], bl[ni][1]);
            }
            #pragma unroll
            for (int mi = 0; mi < 2; mi++)
                #pragma unroll
                for (int ni = 0; ni < 4; ni++) {
                    mma_tf32(acc[mi][ni], ah[mi], bh[ni]);
                    mma_tf32(acc[mi][ni], al[mi], bh[ni]);
                    mma_tf32(acc[mi][ni], ah[mi], bl[ni]);
                }
        }
        __syncthreads();
    }

    // epilogue: bias + silu + dot with ol2w, reduced over the 4-thread column group
    float pr[2][2];   // [mi][rowHalf] partial sums over this thread's columns
    pr[0][0]=0.f; pr[0][1]=0.f; pr[1][0]=0.f; pr[1][1]=0.f;
    #pragma unroll
    for (int mi = 0; mi < 2; mi++)
        #pragma unroll
        for (int ni = 0; ni < 4; ni++) {
            int c0 = nw + ni*8 + tig*2;
            float bb0 = __ldg(&bias[c0]), bb1 = __ldg(&bias[c0+1]);
            float w20 = __ldg(&ol2w[c0]), w21 = __ldg(&ol2w[c0+1]);
            float d0 = acc[mi][ni][0] + bb0;
            float d1 = acc[mi][ni][1] + bb1;
            float d2 = acc[mi][ni][2] + bb0;
            float d3 = acc[mi][ni][3] + bb1;
            d0 = d0 / (1.0f + __expf(-d0));
            d1 = d1 / (1.0f + __expf(-d1));
            d2 = d2 / (1.0f + __expf(-d2));
            d3 = d3 / (1.0f + __expf(-d3));
            pr[mi][0] = fmaf(d0, w20, fmaf(d1, w21, pr[mi][0]));
            pr[mi][1] = fmaf(d2, w20, fmaf(d3, w21, pr[mi][1]));
        }
    // reduce over tig (lane bits 0,1)
    #pragma unroll
    for (int mi = 0; mi < 2; mi++)
        #pragma unroll
        for (int hf = 0; hf < 2; hf++) {
            float p = pr[mi][hf];
            p += __shfl_xor_sync(0xffffffffu, p, 1);
            p += __shfl_xor_sync(0xffffffffu, p, 2);
            pr[mi][hf] = p;
        }
    int cg = w >> 2;    // column group 0/1
    if (tig == 0) {
        #pragma unroll
        for (int mi = 0; mi < 2; mi++) {
            sout[mw + mi*16 + gid][cg]     = pr[mi][0];
            sout[mw + mi*16 + gid + 8][cg] = pr[mi][1];
        }
    }
    __syncthreads();
    if (tid < 128)
        out[rowBase + tid] = sout[tid][0] + sout[tid][1] + __ldg(&ol2b[0]);
}

// ---------------- fused combine (norms*gates^2) + LayerNorm(3H=384) ----------------
__global__ void __launch_bounds__(128) k_combine_outln(const float* __restrict__ og,
                                                       const float* __restrict__ ob) {
    __shared__ float sred[8];
    int n = blockIdx.x;
    int h = threadIdx.x;                  // 0..127
    size_t idx = (size_t)n*HH + h;
    float mi  = g_mix[0*NH+idx];
    float ax  = g_mix[1*NH+idx], ay = g_mix[2*NH+idx], az = g_mix[3*NH+idx];
    float sxx = g_mix[4*NH+idx], sxy = g_mix[5*NH+idx], sxz = g_mix[6*NH+idx];
    float syy = g_mix[7*NH+idx], syz = g_mix[8*NH+idx], szz = g_mix[9*NH+idx];
    float s0 = g_scal[n*384 + 3*h + 0];
    float s1 = g_scal[n*384 + 3*h + 1];
    float s2 = g_scal[n*384 + 3*h + 2];
    float xI = 3.f*mi*mi*s0*s0;
    float xA = 2.f*(ax*ax + ay*ay + az*az)*s1*s1;
    float xS = (sxx*sxx + syy*syy + szz*szz
                + 2.f*(sxy*sxy + sxz*sxz + syz*syz))*s2*s2;

    int lane = h & 31, w = h >> 5;
    float s = warp_sum(xI + xA + xS);
    if (lane == 0) sred[w] = s;
    __syncthreads();
    float mu = (sred[0]+sred[1]+sred[2]+sred[3]) * (1.0f/384.0f);
    float dI = xI-mu, dA = xA-mu, dS = xS-mu;
    float v = warp_sum(dI*dI + dA*dA + dS*dS);
    if (lane == 0) sred[4 + w] = v;
    __syncthreads();
    float var = (sred[4]+sred[5]+sred[6]+sred[7]) * (1.0f/384.0f);
    float rs = rsqrtf(var + 1e-5f);
    g_xln[(size_t)n*384 + h]       = dI*rs*__ldg(&og[h])       + __ldg(&ob[h]);
    g_xln[(size_t)n*384 + 128 + h] = dA*rs*__ldg(&og[128 + h]) + __ldg(&ob[128 + h]);
    g_xln[(size_t)n*384 + 256 + h] = dS*rs*__ldg(&og[256 + h]) + __ldg(&ob[256 + h]);
}

// ---------------- launch: forked graph (side streams joined via events) ----------------
extern "C" void kernel_launch(void* const* d_in, const int* in_sizes, int n_in,
                              void* d_out, int out_size) {
    const float* edge_vec = (const float*)d_in[0];
    const float* emb_w    = (const float*)d_in[1];
    const float* emb2_w   = (const float*)d_in[2];
    const float* emb2_b   = (const float*)d_in[3];
    const float* dp1_w    = (const float*)d_in[4];
    const float* dp1_b    = (const float*)d_in[5];
    const float* dp2_w    = (const float*)d_in[6];
    const float* dp2_b    = (const float*)d_in[7];
    const float* dp3_w    = (const float*)d_in[8];
    const float* dp3_b    = (const float*)d_in[9];
    const float* lt0_w    = (const float*)d_in[10];
    const float* lt1_w    = (const float*)d_in[11];
    const float* lt2_w    = (const float*)d_in[12];
    const float* ls0_w    = (const float*)d_in[13];
    const float* ls0_b    = (const float*)d_in[14];
    const float* ls1_w    = (const float*)d_in[15];
    const float* ls1_b    = (const float*)d_in[16];
    const float* init_g   = (const float*)d_in[17];
    const float* init_b   = (const float*)d_in[18];
    const float* lin_w    = (const float*)d_in[19];
    const float* lin_b    = (const float*)d_in[20];
    const float* outn_g   = (const float*)d_in[21];
    const float* outn_b   = (const float*)d_in[22];
    const float* ol1_w    = (const float*)d_in[23];
    const float* ol1_b    = (const float*)d_in[24];
    const float* ol2_w    = (const float*)d_in[25];
    const float* ol2_b    = (const float*)d_in[26];
    const int*   z        = (const int*)d_in[27];
    const int*   eidx     = (const int*)d_in[28];
    float* out = (float*)d_out;

    float m0   = expf(-4.5f);                 // first RBF mean (exp(-cutoff))
    float dm   = (1.0f - m0) / 31.0f;
    float tmp  = (2.0f/32.0f) * (1.0f - m0);
    float beta = 1.0f / (tmp*tmp);
    float x0   = expf(-5.0f);                 // min of x=exp(-alpha*d) for d<4.5
    float dstep = (1.0f - x0) / (float)(NB - 1);
    float invD  = 1.0f / dstep;

    cudaStream_t sA, sB;
    cudaStreamCreateWithFlags(&sA, cudaStreamNonBlocking);
    cudaStreamCreateWithFlags(&sB, cudaStreamNonBlocking);
    cudaEvent_t eF1, eJ1, eF2, eJ2;
    cudaEventCreateWithFlags(&eF1, cudaEventDisableTiming);
    cudaEventCreateWithFlags(&eJ1, cudaEventDisableTiming);
    cudaEventCreateWithFlags(&eF2, cudaEventDisableTiming);
    cudaEventCreateWithFlags(&eJ2, cudaEventDisableTiming);

    // ---- fork 1: weight-table branch (sA) ∥ edge-sort branch (main) ----
    cudaEventRecord(eF1, 0);
    cudaStreamWaitEvent(sA, eF1, 0);
    k_tables<<<128, 128, 0, sA>>>(emb_w, emb2_w, emb2_b);
    k_btab<<<NB/8, 128, 0, sA>>>(dp1_w, dp2_w, dp3_w, m0, dm, beta, x0, dstep);
    k_pack<<<NB, 128, 0, sA>>>();
    cudaEventRecord(eJ1, sA);

    k_hist<<<EE/256, 256>>>(eidx);
    k_scan<<<1, 1024>>>();
    k_scatter<<<EE/256, 256>>>(eidx, edge_vec, z, x0, invD);
    cudaStreamWaitEvent(0, eJ1, 0);           // join tables/btab/pack before gather

    // ---- gather (critical path): 2 warps/atom, packed fp16 table ----
    k_gather<<<NN/2, 128>>>(dp1_b, dp2_b, dp3_b, z, init_g, init_b);

    // ---- fork 2: mix GEMM (sB, reads g_cm) ∥ gating MLP (main, reads g_nrm) ----
    cudaEventRecord(eF2, 0);
    cudaStreamWaitEvent(sB, eF2, 0);
    k_gemm_mix<<<dim3(128/64, NN/128, 10), 256, 0, sB>>>(lt0_w, lt1_w, lt2_w);
    cudaEventRecord(eJ2, sB);

    k_gemm<1><<<dim3(256/64, NN/128), 256>>>(0, ls0_w, ls0_b, 1, 128, 256);
    k_gemm<1><<<dim3(384/64, NN/128), 256>>>(1, ls1_w, ls1_b, 2, 256, 384);
    cudaStreamWaitEvent(0, eJ2, 0);           // join mix before combine

    // ---- combine + LN(3H), output MLP (final dot fused into last GEMM) ----
    k_combine_outln<<<NN, 128>>>(outn_g, outn_b);
    k_gemm<1><<<dim3(128/64, NN/128), 256>>>(3, lin_w, lin_b, 4, 384, 128);
    k_gemm_last<<<dim3(1, NN/128), 256>>>(ol1_w, ol1_b, ol2_w, ol2_b, out);

    // Destroy only when not capturing (destroying a capturing stream is illegal;
    // during the single capture call we intentionally leak 2 streams + 4 events).
    cudaStreamCaptureStatus cs = cudaStreamCaptureStatusNone;
    cudaStreamIsCapturing(0, &cs);
    if (cs == cudaStreamCaptureStatusNone) {
        cudaStreamDestroy(sA);
        cudaStreamDestroy(sB);
        cudaEventDestroy(eF1);
        cudaEventDestroy(eJ1);
        cudaEventDestroy(eF2);
        cudaEventDestroy(eJ2);
    }
}